// round 3
// baseline (speedup 1.0000x reference)
#include <cuda_runtime.h>
#include <math.h>

#define DD  20
#define TPB 256

typedef unsigned long long u64;

// ---------------- packed f32x2 helpers (sm_103a) ----------------
__device__ __forceinline__ u64 pk(float lo, float hi) {
    u64 r; asm("mov.b64 %0, {%1, %2};" : "=l"(r) : "f"(lo), "f"(hi)); return r;
}
__device__ __forceinline__ void upk(u64 v, float& lo, float& hi) {
    asm("mov.b64 {%0, %1}, %2;" : "=f"(lo), "=f"(hi) : "l"(v));
}
__device__ __forceinline__ u64 fma2(u64 a, u64 b, u64 c) {
    u64 d; asm("fma.rn.f32x2 %0, %1, %2, %3;" : "=l"(d) : "l"(a), "l"(b), "l"(c)); return d;
}
__device__ __forceinline__ u64 relu2(u64 v) {
    float a, b; upk(v, a, b);
    return pk(fmaxf(a, 0.0f), fmaxf(b, 0.0f));
}

// ---------------- device-global scratch (no allocation allowed) ----------------
__device__ double g_pS[16384];
__device__ double g_pQ[16384];

// =====================================================================
// main: per-block weight fold (no setup launch), 2 rows/thread, f32x2
// =====================================================================
__global__ void __launch_bounds__(TPB)
main_kernel(const float* __restrict__ x,
            const float* __restrict__ W,
            const float* __restrict__ b,
            const float* __restrict__ R,
            int B) {
    // staging for the fold
    __shared__ float sWf[DD * DD];
    __shared__ float sRf[DD * DD];
    __shared__ float sbf[DD];
    // folded weights, duplicated {m,m} as u64
    __shared__ __align__(16) u64 sM1[DD * DD];  // M1[k][j] = sum_m W[m,k]*R[m,j]
    __shared__ __align__(16) u64 sT[DD * DD];   // T[i][k]: G_ii on diag, 2*G_ik above, 0 below
    __shared__ u64 sc1[DD];                     // b@R + 1
    __shared__ __align__(16) u64 swcs[DD];      // column sums of W
    __shared__ __align__(16) u64 su2[DD];       // 2 * W^T b
    __shared__ double redS[TPB];
    __shared__ double redQ[TPB];

    const int tid = threadIdx.x;

    // ---- stage W, R, b ----
    for (int i = tid; i < DD * DD; i += TPB) { sWf[i] = W[i]; sRf[i] = R[i]; }
    if (tid < DD) sbf[tid] = b[tid];
    __syncthreads();

    // ---- fold: M1, T(=G doubled-upper-tri), c1, wcs, u2 ----
    for (int i = tid; i < DD * DD; i += TPB) {
        int k = i / DD, j = i % DD;
        float m1 = 0.0f, g = 0.0f;
        #pragma unroll
        for (int m = 0; m < DD; m++) {
            m1 = fmaf(sWf[m * DD + k], sRf[m * DD + j], m1);
            g  = fmaf(sWf[m * DD + k], sWf[m * DD + j], g);
        }
        sM1[i] = pk(m1, m1);
        float t = (j > k) ? (2.0f * g) : ((j == k) ? g : 0.0f);
        sT[i] = pk(t, t);
    }
    if (tid < DD) {
        float c = 1.0f, wcs = 0.0f, u = 0.0f;
        #pragma unroll
        for (int m = 0; m < DD; m++) {
            c   = fmaf(sbf[m], sRf[m * DD + tid], c);
            wcs += sWf[m * DD + tid];
            u   = fmaf(sWf[m * DD + tid], sbf[m], u);
        }
        sc1[tid]  = pk(c, c);
        swcs[tid] = pk(wcs, wcs);
        su2[tid]  = pk(2.0f * u, 2.0f * u);
    }
    __syncthreads();

    // ---- mainloop: 2 rows/thread ----
    long long t    = (long long)blockIdx.x * TPB + tid;
    long long row0 = t * 2;

    float sl = 0.0f, ql = 0.0f;

    if (row0 + 2 <= (long long)B) {
        // load 2 rows (160B contiguous, 16B aligned), pack lanes (row0,row1)
        const float4* xp = (const float4*)(x + row0 * DD);
        u64 xa[DD];
        #pragma unroll
        for (int i = 0; i < 5; i++) {
            float4 A  = xp[i];
            float4 Bv = xp[5 + i];
            xa[4*i+0] = pk(A.x, Bv.x);
            xa[4*i+1] = pk(A.y, Bv.y);
            xa[4*i+2] = pk(A.z, Bv.z);
            xa[4*i+3] = pk(A.w, Bv.w);
        }

        // ---- stage 1: h = relu(x @ M1 + c1) ----
        u64 a[DD];
        #pragma unroll
        for (int j = 0; j < DD; j++) a[j] = sc1[j];
        const ulonglong2* sM1v = (const ulonglong2*)sM1;
        #pragma unroll
        for (int k = 0; k < DD; k++) {
            u64 xv = xa[k];
            #pragma unroll
            for (int jp = 0; jp < DD / 2; jp++) {
                ulonglong2 w = sM1v[k * (DD / 2) + jp];
                a[2*jp+0] = fma2(xv, w.x, a[2*jp+0]);
                a[2*jp+1] = fma2(xv, w.y, a[2*jp+1]);
            }
        }
        #pragma unroll
        for (int j = 0; j < DD; j++) a[j] = relu2(a[j]);

        // ---- linear terms: S += wcs.h ; Q += (2 W^T b).h ----
        u64 s2 = 0ULL, q2 = 0ULL;
        const ulonglong2* swcsv = (const ulonglong2*)swcs;
        const ulonglong2* su2v  = (const ulonglong2*)su2;
        #pragma unroll
        for (int kp = 0; kp < DD / 2; kp++) {
            ulonglong2 wc = swcsv[kp];
            ulonglong2 uu = su2v[kp];
            s2 = fma2(a[2*kp+0], wc.x, s2);
            s2 = fma2(a[2*kp+1], wc.y, s2);
            q2 = fma2(a[2*kp+0], uu.x, q2);
            q2 = fma2(a[2*kp+1], uu.y, q2);
        }

        // ---- quadratic: Q += h^T G h = sum_i h_i * (T h)_i, T upper-tri ----
        #pragma unroll
        for (int i = 0; i < DD; i++) {
            u64 y = 0ULL;
            const int ks = i & ~1;   // row i of T zero below diag; even-aligned start
            #pragma unroll
            for (int k = ks; k < DD; k += 2) {
                ulonglong2 w = *(const ulonglong2*)&sT[i * DD + k];
                y = fma2(a[k],     w.x, y);
                y = fma2(a[k + 1], w.y, y);
            }
            q2 = fma2(a[i], y, q2);
        }

        float slo, shi, qlo, qhi;
        upk(s2, slo, shi); sl = slo + shi;
        upk(q2, qlo, qhi); ql = qlo + qhi;
    } else if (row0 < (long long)B) {
        // scalar tail (unused when B % 2 == 0)
        for (long long r = row0; r < (long long)B && r < row0 + 2; r++) {
            const float* xr = x + r * DD;
            float h[DD];
            #pragma unroll
            for (int j = 0; j < DD; j++) { float lo, hi; upk(sc1[j], lo, hi); h[j] = lo; (void)hi; }
            for (int k = 0; k < DD; k++) {
                float xv = xr[k];
                #pragma unroll
                for (int j = 0; j < DD; j++) { float lo, hi; upk(sM1[k * DD + j], lo, hi); h[j] = fmaf(xv, lo, h[j]); (void)hi; }
            }
            #pragma unroll
            for (int j = 0; j < DD; j++) h[j] = fmaxf(h[j], 0.0f);
            #pragma unroll
            for (int k = 0; k < DD; k++) {
                float wl, wh, ul, uh;
                upk(swcs[k], wl, wh); (void)wh;
                upk(su2[k],  ul, uh); (void)uh;
                sl = fmaf(h[k], wl, sl);
                ql = fmaf(h[k], ul, ql);
            }
            for (int i = 0; i < DD; i++) {
                float y = 0.0f;
                for (int k = i; k < DD; k++) {
                    float wl, wh; upk(sT[i * DD + k], wl, wh); (void)wh;
                    y = fmaf(h[k], wl, y);
                }
                ql = fmaf(h[i], y, ql);
            }
        }
    }

    // deterministic block reduction
    redS[tid] = (double)sl;
    redQ[tid] = (double)ql;
    __syncthreads();
    for (int s = TPB / 2; s > 0; s >>= 1) {
        if (tid < s) { redS[tid] += redS[tid + s]; redQ[tid] += redQ[tid + s]; }
        __syncthreads();
    }
    if (tid == 0) {
        g_pS[blockIdx.x] = redS[0];
        g_pQ[blockIdx.x] = redQ[0];
    }
}

// ---------------- finalize: global reduce + b-terms + scalar postlude ----------------
__global__ void finalize_kernel(float* __restrict__ out,
                                const float* __restrict__ b,
                                int nblocks, int B) {
    __shared__ double sS[256];
    __shared__ double sQ[256];
    int tid = threadIdx.x;
    double s = 0.0, q = 0.0;
    for (int i = tid; i < nblocks; i += 256) { s += g_pS[i]; q += g_pQ[i]; }
    sS[tid] = s; sQ[tid] = q;
    __syncthreads();
    for (int st = 128; st > 0; st >>= 1) {
        if (tid < st) { sS[tid] += sS[tid + st]; sQ[tid] += sQ[tid + st]; }
        __syncthreads();
    }
    if (tid == 0) {
        double sb = 0.0, bb = 0.0;
        #pragma unroll
        for (int m = 0; m < DD; m++) { sb += (double)b[m]; bb += (double)b[m] * (double)b[m]; }
        double S = sS[0] + (double)B * sb;
        double Q = sQ[0] + (double)B * bb;
        float n = (float)sqrt(Q);
        int k = 0;
        while (n > 1.0f && k < 300) { n *= 0.5f; k++; }   // exact halvings in fp32
        float mult = (n < 0.8f) ? 10.0f : 1.0f;
        double scale = ldexp(1.0, -k);
        out[0] = (float)(S * scale * (double)mult);
    }
}

// ---------------- entry point ----------------
extern "C" void kernel_launch(void* const* d_in, const int* in_sizes, int n_in,
                              void* d_out, int out_size) {
    const float* x = (const float*)d_in[0];
    const float* W = (const float*)d_in[1];
    const float* b = (const float*)d_in[2];
    const float* R = (const float*)d_in[3];
    int B = in_sizes[0] / DD;

    long long threads = ((long long)B + 1) / 2;
    int nblocks = (int)((threads + TPB - 1) / TPB);
    if (nblocks > 16384) nblocks = 16384;   // B=2e6 -> 3907 blocks

    main_kernel<<<nblocks, TPB>>>(x, W, b, R, B);
    finalize_kernel<<<1, 256>>>((float*)d_out, b, nblocks, B);
}

// round 4
// speedup vs baseline: 1.0321x; 1.0321x over previous
#include <cuda_runtime.h>
#include <math.h>

#define DD    20
#define TPB   256
#define GRID  592          // 4 blocks/SM on 148 SMs; grid-stride persistent
#define ROWS_PER_TILE (TPB * 2)

typedef unsigned long long u64;

// ---------------- packed f32x2 helpers (sm_103a) ----------------
__device__ __forceinline__ u64 pk(float lo, float hi) {
    u64 r; asm("mov.b64 %0, {%1, %2};" : "=l"(r) : "f"(lo), "f"(hi)); return r;
}
__device__ __forceinline__ void upk(u64 v, float& lo, float& hi) {
    asm("mov.b64 {%0, %1}, %2;" : "=f"(lo), "=f"(hi) : "l"(v));
}
__device__ __forceinline__ u64 fma2(u64 a, u64 b, u64 c) {
    u64 d; asm("fma.rn.f32x2 %0, %1, %2, %3;" : "=l"(d) : "l"(a), "l"(b), "l"(c)); return d;
}
__device__ __forceinline__ u64 relu2(u64 v) {
    float a, b; upk(v, a, b);
    return pk(fmaxf(a, 0.0f), fmaxf(b, 0.0f));
}

// ---------------- device-global scratch (no allocation allowed) ----------------
__device__ double g_pS[1024];
__device__ double g_pQ[1024];
__device__ unsigned int g_ticket = 0;   // reset by last block each launch

// =====================================================================
// single fused kernel: fold + grid-stride mainloop + last-block finalize
// =====================================================================
__global__ void __launch_bounds__(TPB)
main_kernel(const float* __restrict__ x,
            const float* __restrict__ W,
            const float* __restrict__ b,
            const float* __restrict__ R,
            float* __restrict__ out,
            int B) {
    // staging for the fold
    __shared__ float sWf[DD * DD];
    __shared__ float sRf[DD * DD];
    __shared__ float sbf[DD];
    // folded weights, duplicated {m,m} as u64
    __shared__ __align__(16) u64 sM1[DD * DD];  // M1[k][j] = sum_m W[m,k]*R[m,j]
    __shared__ __align__(16) u64 sT[DD * DD];   // T[i][k]: G_ii diag, 2*G_ik above, 0 below
    __shared__ u64 sc1[DD];                     // b@R + 1
    __shared__ __align__(16) u64 swcs[DD];      // column sums of W
    __shared__ __align__(16) u64 su2[DD];       // 2 * W^T b
    __shared__ double redS[TPB];
    __shared__ double redQ[TPB];
    __shared__ int sIsLast;

    const int tid = threadIdx.x;

    // ---- stage W, R, b ----
    for (int i = tid; i < DD * DD; i += TPB) { sWf[i] = W[i]; sRf[i] = R[i]; }
    if (tid < DD) sbf[tid] = b[tid];
    __syncthreads();

    // ---- fold (once per block, amortized over ~7 tiles) ----
    for (int i = tid; i < DD * DD; i += TPB) {
        int k = i / DD, j = i % DD;
        float m1 = 0.0f, g = 0.0f;
        #pragma unroll
        for (int m = 0; m < DD; m++) {
            m1 = fmaf(sWf[m * DD + k], sRf[m * DD + j], m1);
            g  = fmaf(sWf[m * DD + k], sWf[m * DD + j], g);
        }
        sM1[i] = pk(m1, m1);
        float t = (j > k) ? (2.0f * g) : ((j == k) ? g : 0.0f);
        sT[i] = pk(t, t);
    }
    if (tid < DD) {
        float c = 1.0f, wcs = 0.0f, u = 0.0f;
        #pragma unroll
        for (int m = 0; m < DD; m++) {
            c   = fmaf(sbf[m], sRf[m * DD + tid], c);
            wcs += sWf[m * DD + tid];
            u   = fmaf(sWf[m * DD + tid], sbf[m], u);
        }
        sc1[tid]  = pk(c, c);
        swcs[tid] = pk(wcs, wcs);
        su2[tid]  = pk(2.0f * u, 2.0f * u);
    }
    __syncthreads();

    // ---- grid-stride mainloop: 2 rows/thread/tile ----
    float sl = 0.0f, ql = 0.0f;
    const long long rowsTotal = (long long)B;

    for (long long tile = blockIdx.x; tile * ROWS_PER_TILE < rowsTotal; tile += GRID) {
        long long row0 = tile * ROWS_PER_TILE + (long long)tid * 2;
        if (row0 + 2 <= rowsTotal) {
            // load 2 rows (160B contiguous, 16B aligned), pack lanes (row0,row1)
            const float4* xp = (const float4*)(x + row0 * DD);
            u64 xa[DD];
            #pragma unroll
            for (int i = 0; i < 5; i++) {
                float4 A  = xp[i];
                float4 Bv = xp[5 + i];
                xa[4*i+0] = pk(A.x, Bv.x);
                xa[4*i+1] = pk(A.y, Bv.y);
                xa[4*i+2] = pk(A.z, Bv.z);
                xa[4*i+3] = pk(A.w, Bv.w);
            }

            // stage 1: h = relu(x @ M1 + c1)
            u64 a[DD];
            #pragma unroll
            for (int j = 0; j < DD; j++) a[j] = sc1[j];
            const ulonglong2* sM1v = (const ulonglong2*)sM1;
            #pragma unroll
            for (int k = 0; k < DD; k++) {
                u64 xv = xa[k];
                #pragma unroll
                for (int jp = 0; jp < DD / 2; jp++) {
                    ulonglong2 w = sM1v[k * (DD / 2) + jp];
                    a[2*jp+0] = fma2(xv, w.x, a[2*jp+0]);
                    a[2*jp+1] = fma2(xv, w.y, a[2*jp+1]);
                }
            }
            #pragma unroll
            for (int j = 0; j < DD; j++) a[j] = relu2(a[j]);

            // linear terms: S += wcs.h ; Q += (2 W^T b).h
            u64 s2 = 0ULL, q2 = 0ULL;
            const ulonglong2* swcsv = (const ulonglong2*)swcs;
            const ulonglong2* su2v  = (const ulonglong2*)su2;
            #pragma unroll
            for (int kp = 0; kp < DD / 2; kp++) {
                ulonglong2 wc = swcsv[kp];
                ulonglong2 uu = su2v[kp];
                s2 = fma2(a[2*kp+0], wc.x, s2);
                s2 = fma2(a[2*kp+1], wc.y, s2);
                q2 = fma2(a[2*kp+0], uu.x, q2);
                q2 = fma2(a[2*kp+1], uu.y, q2);
            }

            // quadratic: Q += h^T G h via upper-tri T
            #pragma unroll
            for (int i = 0; i < DD; i++) {
                u64 y = 0ULL;
                const int ks = i & ~1;
                #pragma unroll
                for (int k = ks; k < DD; k += 2) {
                    ulonglong2 w = *(const ulonglong2*)&sT[i * DD + k];
                    y = fma2(a[k],     w.x, y);
                    y = fma2(a[k + 1], w.y, y);
                }
                q2 = fma2(a[i], y, q2);
            }

            float slo, shi, qlo, qhi;
            upk(s2, slo, shi); sl += slo + shi;
            upk(q2, qlo, qhi); ql += qlo + qhi;
        } else if (row0 < rowsTotal) {
            // scalar tail (only when B odd / partial pair)
            for (long long r = row0; r < rowsTotal && r < row0 + 2; r++) {
                const float* xr = x + r * DD;
                float h[DD];
                #pragma unroll
                for (int j = 0; j < DD; j++) { float lo, hi; upk(sc1[j], lo, hi); h[j] = lo; (void)hi; }
                for (int k = 0; k < DD; k++) {
                    float xv = xr[k];
                    #pragma unroll
                    for (int j = 0; j < DD; j++) { float lo, hi; upk(sM1[k * DD + j], lo, hi); h[j] = fmaf(xv, lo, h[j]); (void)hi; }
                }
                #pragma unroll
                for (int j = 0; j < DD; j++) h[j] = fmaxf(h[j], 0.0f);
                #pragma unroll
                for (int k = 0; k < DD; k++) {
                    float wl, wh, ul, uh;
                    upk(swcs[k], wl, wh); (void)wh;
                    upk(su2[k],  ul, uh); (void)uh;
                    sl = fmaf(h[k], wl, sl);
                    ql = fmaf(h[k], ul, ql);
                }
                for (int i = 0; i < DD; i++) {
                    float y = 0.0f;
                    for (int k = i; k < DD; k++) {
                        float wl, wh; upk(sT[i * DD + k], wl, wh); (void)wh;
                        y = fmaf(h[k], wl, y);
                    }
                    ql = fmaf(h[i], y, ql);
                }
            }
        }
    }

    // ---- deterministic block reduction ----
    redS[tid] = (double)sl;
    redQ[tid] = (double)ql;
    __syncthreads();
    for (int s = TPB / 2; s > 0; s >>= 1) {
        if (tid < s) { redS[tid] += redS[tid + s]; redQ[tid] += redQ[tid + s]; }
        __syncthreads();
    }
    if (tid == 0) {
        g_pS[blockIdx.x] = redS[0];
        g_pQ[blockIdx.x] = redQ[0];
        __threadfence();
        unsigned int t = atomicAdd(&g_ticket, 1u);
        sIsLast = (t == (unsigned int)(GRID - 1)) ? 1 : 0;
    }
    __syncthreads();

    // ---- last block: global reduce (partials L2-hot) + scalar postlude ----
    if (sIsLast) {
        __threadfence();   // ensure visibility of all partials
        double s = 0.0, q = 0.0;
        for (int i = tid; i < GRID; i += TPB) { s += g_pS[i]; q += g_pQ[i]; }
        redS[tid] = s; redQ[tid] = q;
        __syncthreads();
        for (int st = TPB / 2; st > 0; st >>= 1) {
            if (tid < st) { redS[tid] += redS[tid + st]; redQ[tid] += redQ[tid + st]; }
            __syncthreads();
        }
        if (tid == 0) {
            double sb = 0.0, bb = 0.0;
            #pragma unroll
            for (int m = 0; m < DD; m++) { sb += (double)sbf[m]; bb += (double)sbf[m] * (double)sbf[m]; }
            double S = redS[0] + (double)B * sb;
            double Q = redQ[0] + (double)B * bb;
            float n = (float)sqrt(Q);
            int k = 0;
            while (n > 1.0f && k < 300) { n *= 0.5f; k++; }   // exact halvings in fp32
            float mult = (n < 0.8f) ? 10.0f : 1.0f;
            double scale = ldexp(1.0, -k);
            out[0] = (float)(S * scale * (double)mult);
            g_ticket = 0;   // reset for next (graph-replayed) launch
        }
    }
}

// ---------------- entry point ----------------
extern "C" void kernel_launch(void* const* d_in, const int* in_sizes, int n_in,
                              void* d_out, int out_size) {
    const float* x = (const float*)d_in[0];
    const float* W = (const float*)d_in[1];
    const float* b = (const float*)d_in[2];
    const float* R = (const float*)d_in[3];
    int B = in_sizes[0] / DD;

    main_kernel<<<GRID, TPB>>>(x, W, b, R, (float*)d_out, B);
}

// round 5
// speedup vs baseline: 1.0678x; 1.0346x over previous
#include <cuda_runtime.h>
#include <math.h>

#define DD    20
#define TPB   256
#define GRID  592          // 2 blocks/SM * 148 SMs * 2 waves
#define ROWS_PER_TILE (TPB * 2)

typedef unsigned long long u64;

// ---------------- packed f32x2 helpers (sm_103a) ----------------
__device__ __forceinline__ u64 pk(float lo, float hi) {
    u64 r; asm("mov.b64 %0, {%1, %2};" : "=l"(r) : "f"(lo), "f"(hi)); return r;
}
__device__ __forceinline__ void upk(u64 v, float& lo, float& hi) {
    asm("mov.b64 {%0, %1}, %2;" : "=f"(lo), "=f"(hi) : "l"(v));
}
__device__ __forceinline__ u64 fma2(u64 a, u64 b, u64 c) {
    u64 d; asm("fma.rn.f32x2 %0, %1, %2, %3;" : "=l"(d) : "l"(a), "l"(b), "l"(c)); return d;
}
__device__ __forceinline__ u64 relu2(u64 v) {
    float a, b; upk(v, a, b);
    return pk(fmaxf(a, 0.0f), fmaxf(b, 0.0f));
}

// ---------------- device-global scratch (no allocation allowed) ----------------
__device__ double g_pS[1024];
__device__ double g_pQ[1024];
__device__ unsigned int g_ticket = 0;   // reset by last block each launch

// =====================================================================
// single fused persistent kernel, 2 blocks/SM, streamed x, f32x2 math
// =====================================================================
__global__ void __launch_bounds__(TPB, 2)
main_kernel(const float* __restrict__ x,
            const float* __restrict__ W,
            const float* __restrict__ b,
            const float* __restrict__ R,
            float* __restrict__ out,
            int B) {
    // staging for the fold
    __shared__ float sWf[DD * DD];
    __shared__ float sRf[DD * DD];
    __shared__ float sbf[DD];
    // folded weights, duplicated {m,m} as u64
    __shared__ __align__(16) u64 sM1[DD * DD];  // M1[k][j] = sum_m W[m,k]*R[m,j]
    __shared__ __align__(16) u64 sT[DD * DD];   // T[i][k]: G_ii diag, 2*G_ik above, 0 below
    __shared__ u64 sc1[DD];                     // b@R + 1
    __shared__ __align__(16) u64 swcs[DD];      // column sums of W
    __shared__ __align__(16) u64 su2[DD];       // 2 * W^T b
    __shared__ double redS[TPB];
    __shared__ double redQ[TPB];
    __shared__ int sIsLast;

    const int tid = threadIdx.x;

    // ---- stage W, R, b ----
    for (int i = tid; i < DD * DD; i += TPB) { sWf[i] = W[i]; sRf[i] = R[i]; }
    if (tid < DD) sbf[tid] = b[tid];
    __syncthreads();

    // ---- fold (once per block) ----
    for (int i = tid; i < DD * DD; i += TPB) {
        int k = i / DD, j = i % DD;
        float m1 = 0.0f, g = 0.0f;
        #pragma unroll
        for (int m = 0; m < DD; m++) {
            m1 = fmaf(sWf[m * DD + k], sRf[m * DD + j], m1);
            g  = fmaf(sWf[m * DD + k], sWf[m * DD + j], g);
        }
        sM1[i] = pk(m1, m1);
        float t = (j > k) ? (2.0f * g) : ((j == k) ? g : 0.0f);
        sT[i] = pk(t, t);
    }
    if (tid < DD) {
        float c = 1.0f, wcs = 0.0f, u = 0.0f;
        #pragma unroll
        for (int m = 0; m < DD; m++) {
            c   = fmaf(sbf[m], sRf[m * DD + tid], c);
            wcs += sWf[m * DD + tid];
            u   = fmaf(sWf[m * DD + tid], sbf[m], u);
        }
        sc1[tid]  = pk(c, c);
        swcs[tid] = pk(wcs, wcs);
        su2[tid]  = pk(2.0f * u, 2.0f * u);
    }
    __syncthreads();

    // ---- grid-stride mainloop: 2 rows/thread/tile, streamed x ----
    float sl = 0.0f, ql = 0.0f;
    const long long rowsTotal = (long long)B;

    #pragma unroll 1
    for (long long tile = blockIdx.x; tile * ROWS_PER_TILE < rowsTotal; tile += GRID) {
        long long row0 = tile * ROWS_PER_TILE + (long long)tid * 2;
        if (row0 + 2 <= rowsTotal) {
            const float4* xp = (const float4*)(x + row0 * DD);

            // accumulators
            u64 a[DD];
            #pragma unroll
            for (int j = 0; j < DD; j++) a[j] = sc1[j];

            const ulonglong2* sM1v = (const ulonglong2*)sM1;

            // stream x: consume one float4-pair (4 k-steps) at a time,
            // prefetching the next pair. Peak live: a[20] + 2 pairs + temps.
            float4 A0 = xp[0], B0 = xp[5];
            #pragma unroll
            for (int i = 0; i < 5; i++) {
                float4 A1, B1;
                if (i < 4) { A1 = xp[i + 1]; B1 = xp[6 + i]; }
                #pragma unroll
                for (int c = 0; c < 4; c++) {
                    const int k = 4 * i + c;
                    u64 xv = pk(c == 0 ? A0.x : c == 1 ? A0.y : c == 2 ? A0.z : A0.w,
                                c == 0 ? B0.x : c == 1 ? B0.y : c == 2 ? B0.z : B0.w);
                    #pragma unroll
                    for (int jp = 0; jp < DD / 2; jp++) {
                        ulonglong2 w = sM1v[k * (DD / 2) + jp];
                        a[2*jp+0] = fma2(xv, w.x, a[2*jp+0]);
                        a[2*jp+1] = fma2(xv, w.y, a[2*jp+1]);
                    }
                }
                A0 = A1; B0 = B1;
            }
            #pragma unroll
            for (int j = 0; j < DD; j++) a[j] = relu2(a[j]);

            // linear terms: S += wcs.h ; Q += (2 W^T b).h
            u64 s2 = 0ULL, q2 = 0ULL;
            const ulonglong2* swcsv = (const ulonglong2*)swcs;
            const ulonglong2* su2v  = (const ulonglong2*)su2;
            #pragma unroll
            for (int kp = 0; kp < DD / 2; kp++) {
                ulonglong2 wc = swcsv[kp];
                ulonglong2 uu = su2v[kp];
                s2 = fma2(a[2*kp+0], wc.x, s2);
                s2 = fma2(a[2*kp+1], wc.y, s2);
                q2 = fma2(a[2*kp+0], uu.x, q2);
                q2 = fma2(a[2*kp+1], uu.y, q2);
            }

            // quadratic: Q += h^T G h via upper-tri T
            #pragma unroll
            for (int i = 0; i < DD; i++) {
                u64 y = 0ULL;
                const int ks = i & ~1;
                #pragma unroll
                for (int k = ks; k < DD; k += 2) {
                    ulonglong2 w = *(const ulonglong2*)&sT[i * DD + k];
                    y = fma2(a[k],     w.x, y);
                    y = fma2(a[k + 1], w.y, y);
                }
                q2 = fma2(a[i], y, q2);
            }

            float slo, shi, qlo, qhi;
            upk(s2, slo, shi); sl += slo + shi;
            upk(q2, qlo, qhi); ql += qlo + qhi;
        } else if (row0 < rowsTotal) {
            // scalar tail (only when B odd / partial pair)
            for (long long r = row0; r < rowsTotal && r < row0 + 2; r++) {
                const float* xr = x + r * DD;
                float h[DD];
                #pragma unroll
                for (int j = 0; j < DD; j++) { float lo, hi; upk(sc1[j], lo, hi); h[j] = lo; (void)hi; }
                for (int k = 0; k < DD; k++) {
                    float xv = xr[k];
                    #pragma unroll
                    for (int j = 0; j < DD; j++) { float lo, hi; upk(sM1[k * DD + j], lo, hi); h[j] = fmaf(xv, lo, h[j]); (void)hi; }
                }
                #pragma unroll
                for (int j = 0; j < DD; j++) h[j] = fmaxf(h[j], 0.0f);
                #pragma unroll
                for (int k = 0; k < DD; k++) {
                    float wl, wh, ul, uh;
                    upk(swcs[k], wl, wh); (void)wh;
                    upk(su2[k],  ul, uh); (void)uh;
                    sl = fmaf(h[k], wl, sl);
                    ql = fmaf(h[k], ul, ql);
                }
                for (int i = 0; i < DD; i++) {
                    float y = 0.0f;
                    for (int k = i; k < DD; k++) {
                        float wl, wh; upk(sT[i * DD + k], wl, wh); (void)wh;
                        y = fmaf(h[k], wl, y);
                    }
                    ql = fmaf(h[i], y, ql);
                }
            }
        }
    }

    // ---- deterministic block reduction ----
    redS[tid] = (double)sl;
    redQ[tid] = (double)ql;
    __syncthreads();
    for (int s = TPB / 2; s > 0; s >>= 1) {
        if (tid < s) { redS[tid] += redS[tid + s]; redQ[tid] += redQ[tid + s]; }
        __syncthreads();
    }
    if (tid == 0) {
        g_pS[blockIdx.x] = redS[0];
        g_pQ[blockIdx.x] = redQ[0];
        __threadfence();
        unsigned int t = atomicAdd(&g_ticket, 1u);
        sIsLast = (t == (unsigned int)(GRID - 1)) ? 1 : 0;
    }
    __syncthreads();

    // ---- last block: global reduce + scalar postlude ----
    if (sIsLast) {
        __threadfence();
        double s = 0.0, q = 0.0;
        for (int i = tid; i < GRID; i += TPB) { s += g_pS[i]; q += g_pQ[i]; }
        redS[tid] = s; redQ[tid] = q;
        __syncthreads();
        for (int st = TPB / 2; st > 0; st >>= 1) {
            if (tid < st) { redS[tid] += redS[tid + st]; redQ[tid] += redQ[tid + st]; }
            __syncthreads();
        }
        if (tid == 0) {
            double sb = 0.0, bb = 0.0;
            #pragma unroll
            for (int m = 0; m < DD; m++) { sb += (double)sbf[m]; bb += (double)sbf[m] * (double)sbf[m]; }
            double S = redS[0] + (double)B * sb;
            double Q = redQ[0] + (double)B * bb;
            float n = (float)sqrt(Q);
            int k = 0;
            while (n > 1.0f && k < 300) { n *= 0.5f; k++; }   // exact halvings in fp32
            float mult = (n < 0.8f) ? 10.0f : 1.0f;
            double scale = ldexp(1.0, -k);
            out[0] = (float)(S * scale * (double)mult);
            g_ticket = 0;   // reset for next (graph-replayed) launch
        }
    }
}

// ---------------- entry point ----------------
extern "C" void kernel_launch(void* const* d_in, const int* in_sizes, int n_in,
                              void* d_out, int out_size) {
    const float* x = (const float*)d_in[0];
    const float* W = (const float*)d_in[1];
    const float* b = (const float*)d_in[2];
    const float* R = (const float*)d_in[3];
    int B = in_sizes[0] / DD;

    main_kernel<<<GRID, TPB>>>(x, W, b, R, (float*)d_out, B);
}

// round 6
// speedup vs baseline: 1.1082x; 1.0378x over previous
#include <cuda_runtime.h>
#include <math.h>

#define DD    20
#define TPB   128
#define GRID  444           // 3 blocks/SM * 148 SMs
#define ROWS_PER_TILE (TPB * 4)

typedef unsigned long long u64;

// ---------------- packed f32x2 helpers (sm_103a) ----------------
__device__ __forceinline__ u64 pk(float lo, float hi) {
    u64 r; asm("mov.b64 %0, {%1, %2};" : "=l"(r) : "f"(lo), "f"(hi)); return r;
}
__device__ __forceinline__ void upk(u64 v, float& lo, float& hi) {
    asm("mov.b64 {%0, %1}, %2;" : "=f"(lo), "=f"(hi) : "l"(v));
}
__device__ __forceinline__ u64 fma2(u64 a, u64 b, u64 c) {
    u64 d; asm("fma.rn.f32x2 %0, %1, %2, %3;" : "=l"(d) : "l"(a), "l"(b), "l"(c)); return d;
}
__device__ __forceinline__ u64 relu2(u64 v) {
    float a, b; upk(v, a, b);
    return pk(fmaxf(a, 0.0f), fmaxf(b, 0.0f));
}

// ---------------- device-global scratch (no allocation allowed) ----------------
__device__ double g_pS[512];
__device__ double g_pQ[512];
__device__ unsigned int g_ticket = 0;

// =====================================================================
// fused persistent kernel: 4 rows/thread (2 f32x2 pairs per weight load)
// =====================================================================
__global__ void __launch_bounds__(TPB, 3)
main_kernel(const float* __restrict__ x,
            const float* __restrict__ W,
            const float* __restrict__ b,
            const float* __restrict__ R,
            float* __restrict__ out,
            int B) {
    __shared__ float sWf[DD * DD];
    __shared__ float sRf[DD * DD];
    __shared__ float sbf[DD];
    __shared__ __align__(16) u64 sM1[DD * DD];  // folded W∘R, dup {m,m}
    __shared__ __align__(16) u64 sT[DD * DD];   // G_ii diag, 2*G_ik above, 0 below
    __shared__ u64 sc1[DD];                     // b@R + 1
    __shared__ __align__(16) u64 swcs[DD];      // column sums of W
    __shared__ __align__(16) u64 su2[DD];       // 2 * W^T b
    __shared__ double redS[TPB];
    __shared__ double redQ[TPB];
    __shared__ int sIsLast;

    const int tid = threadIdx.x;

    // ---- stage W, R, b ----
    for (int i = tid; i < DD * DD; i += TPB) { sWf[i] = W[i]; sRf[i] = R[i]; }
    if (tid < DD) sbf[tid] = b[tid];
    __syncthreads();

    // ---- fold (once per block) ----
    for (int i = tid; i < DD * DD; i += TPB) {
        int k = i / DD, j = i % DD;
        float m1 = 0.0f, g = 0.0f;
        #pragma unroll
        for (int m = 0; m < DD; m++) {
            m1 = fmaf(sWf[m * DD + k], sRf[m * DD + j], m1);
            g  = fmaf(sWf[m * DD + k], sWf[m * DD + j], g);
        }
        sM1[i] = pk(m1, m1);
        float t = (j > k) ? (2.0f * g) : ((j == k) ? g : 0.0f);
        sT[i] = pk(t, t);
    }
    if (tid < DD) {
        float c = 1.0f, wcs = 0.0f, u = 0.0f;
        #pragma unroll
        for (int m = 0; m < DD; m++) {
            c   = fmaf(sbf[m], sRf[m * DD + tid], c);
            wcs += sWf[m * DD + tid];
            u   = fmaf(sWf[m * DD + tid], sbf[m], u);
        }
        sc1[tid]  = pk(c, c);
        swcs[tid] = pk(wcs, wcs);
        su2[tid]  = pk(2.0f * u, 2.0f * u);
    }
    __syncthreads();

    // ---- grid-stride mainloop: 4 rows/thread/tile ----
    float sl = 0.0f, ql = 0.0f;
    const long long rowsTotal = (long long)B;

    #pragma unroll 1
    for (long long tile = blockIdx.x; tile * ROWS_PER_TILE < rowsTotal; tile += GRID) {
        long long row0 = tile * ROWS_PER_TILE + (long long)tid * 4;
        if (row0 + 4 <= rowsTotal) {
            const float4* xp = (const float4*)(x + row0 * DD);

            u64 a0[DD], a1[DD];   // pair (r0,r1) and (r2,r3)
            #pragma unroll
            for (int j = 0; j < DD; j++) { a0[j] = sc1[j]; a1[j] = sc1[j]; }

            const ulonglong2* sM1v = (const ulonglong2*)sM1;

            // stream x: 4 float4 per i-step (one per row), prefetch next step
            float4 A0 = xp[0], B0 = xp[5], C0 = xp[10], D0 = xp[15];
            #pragma unroll
            for (int i = 0; i < 5; i++) {
                float4 A1, B1, C1, D1;
                if (i < 4) { A1 = xp[i+1]; B1 = xp[6+i]; C1 = xp[11+i]; D1 = xp[16+i]; }
                #pragma unroll
                for (int c = 0; c < 4; c++) {
                    const int k = 4 * i + c;
                    u64 xv0 = pk(c==0?A0.x:c==1?A0.y:c==2?A0.z:A0.w,
                                 c==0?B0.x:c==1?B0.y:c==2?B0.z:B0.w);
                    u64 xv1 = pk(c==0?C0.x:c==1?C0.y:c==2?C0.z:C0.w,
                                 c==0?D0.x:c==1?D0.y:c==2?D0.z:D0.w);
                    #pragma unroll
                    for (int jp = 0; jp < DD / 2; jp++) {
                        ulonglong2 w = sM1v[k * (DD / 2) + jp];
                        a0[2*jp+0] = fma2(xv0, w.x, a0[2*jp+0]);
                        a1[2*jp+0] = fma2(xv1, w.x, a1[2*jp+0]);
                        a0[2*jp+1] = fma2(xv0, w.y, a0[2*jp+1]);
                        a1[2*jp+1] = fma2(xv1, w.y, a1[2*jp+1]);
                    }
                }
                A0 = A1; B0 = B1; C0 = C1; D0 = D1;
            }
            #pragma unroll
            for (int j = 0; j < DD; j++) { a0[j] = relu2(a0[j]); a1[j] = relu2(a1[j]); }

            // linear terms: S += wcs.h ; Q += (2 W^T b).h
            u64 s20 = 0ULL, s21 = 0ULL, q20 = 0ULL, q21 = 0ULL;
            const ulonglong2* swcsv = (const ulonglong2*)swcs;
            const ulonglong2* su2v  = (const ulonglong2*)su2;
            #pragma unroll
            for (int kp = 0; kp < DD / 2; kp++) {
                ulonglong2 wc = swcsv[kp];
                ulonglong2 uu = su2v[kp];
                s20 = fma2(a0[2*kp+0], wc.x, s20);  s20 = fma2(a0[2*kp+1], wc.y, s20);
                s21 = fma2(a1[2*kp+0], wc.x, s21);  s21 = fma2(a1[2*kp+1], wc.y, s21);
                q20 = fma2(a0[2*kp+0], uu.x, q20);  q20 = fma2(a0[2*kp+1], uu.y, q20);
                q21 = fma2(a1[2*kp+0], uu.x, q21);  q21 = fma2(a1[2*kp+1], uu.y, q21);
            }

            // quadratic: Q += h^T G h via upper-tri T (both pairs per load)
            #pragma unroll
            for (int i = 0; i < DD; i++) {
                u64 y0 = 0ULL, y1 = 0ULL;
                const int ks = i & ~1;
                #pragma unroll
                for (int k = ks; k < DD; k += 2) {
                    ulonglong2 w = *(const ulonglong2*)&sT[i * DD + k];
                    y0 = fma2(a0[k],     w.x, y0);
                    y1 = fma2(a1[k],     w.x, y1);
                    y0 = fma2(a0[k + 1], w.y, y0);
                    y1 = fma2(a1[k + 1], w.y, y1);
                }
                q20 = fma2(a0[i], y0, q20);
                q21 = fma2(a1[i], y1, q21);
            }

            float lo, hi;
            upk(s20, lo, hi); sl += lo + hi;
            upk(s21, lo, hi); sl += lo + hi;
            upk(q20, lo, hi); ql += lo + hi;
            upk(q21, lo, hi); ql += lo + hi;
        } else if (row0 < rowsTotal) {
            // scalar tail
            for (long long r = row0; r < rowsTotal && r < row0 + 4; r++) {
                const float* xr = x + r * DD;
                float h[DD];
                #pragma unroll
                for (int j = 0; j < DD; j++) { float lo, hi; upk(sc1[j], lo, hi); h[j] = lo; (void)hi; }
                for (int k = 0; k < DD; k++) {
                    float xv = xr[k];
                    #pragma unroll
                    for (int j = 0; j < DD; j++) { float lo, hi; upk(sM1[k * DD + j], lo, hi); h[j] = fmaf(xv, lo, h[j]); (void)hi; }
                }
                #pragma unroll
                for (int j = 0; j < DD; j++) h[j] = fmaxf(h[j], 0.0f);
                #pragma unroll
                for (int k = 0; k < DD; k++) {
                    float wl, wh, ul, uh;
                    upk(swcs[k], wl, wh); (void)wh;
                    upk(su2[k],  ul, uh); (void)uh;
                    sl = fmaf(h[k], wl, sl);
                    ql = fmaf(h[k], ul, ql);
                }
                for (int i = 0; i < DD; i++) {
                    float y = 0.0f;
                    for (int k = i; k < DD; k++) {
                        float wl, wh; upk(sT[i * DD + k], wl, wh); (void)wh;
                        y = fmaf(h[k], wl, y);
                    }
                    ql = fmaf(h[i], y, ql);
                }
            }
        }
    }

    // ---- deterministic block reduction ----
    redS[tid] = (double)sl;
    redQ[tid] = (double)ql;
    __syncthreads();
    for (int s = TPB / 2; s > 0; s >>= 1) {
        if (tid < s) { redS[tid] += redS[tid + s]; redQ[tid] += redQ[tid + s]; }
        __syncthreads();
    }
    if (tid == 0) {
        g_pS[blockIdx.x] = redS[0];
        g_pQ[blockIdx.x] = redQ[0];
        __threadfence();
        unsigned int t = atomicAdd(&g_ticket, 1u);
        sIsLast = (t == (unsigned int)(GRID - 1)) ? 1 : 0;
    }
    __syncthreads();

    // ---- last block: global reduce + scalar postlude ----
    if (sIsLast) {
        __threadfence();
        double s = 0.0, q = 0.0;
        for (int i = tid; i < GRID; i += TPB) { s += g_pS[i]; q += g_pQ[i]; }
        redS[tid] = s; redQ[tid] = q;
        __syncthreads();
        for (int st = TPB / 2; st > 0; st >>= 1) {
            if (tid < st) { redS[tid] += redS[tid + st]; redQ[tid] += redQ[tid + st]; }
            __syncthreads();
        }
        if (tid == 0) {
            double sb = 0.0, bb = 0.0;
            #pragma unroll
            for (int m = 0; m < DD; m++) { sb += (double)sbf[m]; bb += (double)sbf[m] * (double)sbf[m]; }
            double S = redS[0] + (double)B * sb;
            double Q = redQ[0] + (double)B * bb;
            float n = (float)sqrt(Q);
            int k = 0;
            while (n > 1.0f && k < 300) { n *= 0.5f; k++; }   // exact halvings in fp32
            float mult = (n < 0.8f) ? 10.0f : 1.0f;
            double scale = ldexp(1.0, -k);
            out[0] = (float)(S * scale * (double)mult);
            g_ticket = 0;
        }
    }
}

// ---------------- entry point ----------------
extern "C" void kernel_launch(void* const* d_in, const int* in_sizes, int n_in,
                              void* d_out, int out_size) {
    const float* x = (const float*)d_in[0];
    const float* W = (const float*)d_in[1];
    const float* b = (const float*)d_in[2];
    const float* R = (const float*)d_in[3];
    int B = in_sizes[0] / DD;

    main_kernel<<<GRID, TPB>>>(x, W, b, R, (float*)d_out, B);
}

// round 7
// speedup vs baseline: 1.4363x; 1.2961x over previous
#include <cuda_runtime.h>
#include <math.h>

#define DD    20
#define TPB   128
#define GRID  444           // 3 blocks/SM * 148 SMs
#define ROWS_PER_TILE (TPB * 4)

typedef unsigned long long u64;

// ---------------- packed f32x2 helpers (sm_103a) ----------------
__device__ __forceinline__ u64 pk(float lo, float hi) {
    u64 r; asm("mov.b64 %0, {%1, %2};" : "=l"(r) : "f"(lo), "f"(hi)); return r;
}
__device__ __forceinline__ void upk(u64 v, float& lo, float& hi) {
    asm("mov.b64 {%0, %1}, %2;" : "=f"(lo), "=f"(hi) : "l"(v));
}
__device__ __forceinline__ u64 fma2(u64 a, u64 b, u64 c) {
    u64 d; asm("fma.rn.f32x2 %0, %1, %2, %3;" : "=l"(d) : "l"(a), "l"(b), "l"(c)); return d;
}
__device__ __forceinline__ u64 relu2(u64 v) {
    float a, b; upk(v, a, b);
    return pk(fmaxf(a, 0.0f), fmaxf(b, 0.0f));
}
__device__ __forceinline__ float comp(const float4& q, int c) {
    return c == 0 ? q.x : c == 1 ? q.y : c == 2 ? q.z : q.w;
}

// ---------------- device-global scratch ----------------
__device__ double g_pS[512];
__device__ double g_pQ[512];
__device__ unsigned int g_ticket = 0;

// =====================================================================
// fused persistent kernel: 4 rows/thread, j-pair packing, undupped weights
// =====================================================================
__global__ void __launch_bounds__(TPB, 3)
main_kernel(const float* __restrict__ x,
            const float* __restrict__ W,
            const float* __restrict__ b,
            const float* __restrict__ R,
            float* __restrict__ out,
            int B) {
    __shared__ float sWf[DD * DD];
    __shared__ float sRf[DD * DD];
    __shared__ float sbf[DD];
    // undupped float weight arrays (j-contiguous pairs)
    __shared__ __align__(16) float sM1f[DD * DD];  // M1[k][j]
    __shared__ __align__(16) float sTf[DD * DD];   // T[i][k]: G_ii diag, 2G above, 0 below
    __shared__ __align__(16) float sc1f[DD];       // b@R + 1
    __shared__ __align__(16) float swcsf[DD];      // column sums of W
    __shared__ __align__(16) float su2f[DD];       // 2 * W^T b
    __shared__ double redS[TPB];
    __shared__ double redQ[TPB];
    __shared__ int sIsLast;

    const int tid = threadIdx.x;

    // ---- stage W, R, b ----
    for (int i = tid; i < DD * DD; i += TPB) { sWf[i] = W[i]; sRf[i] = R[i]; }
    if (tid < DD) sbf[tid] = b[tid];
    __syncthreads();

    // ---- fold (once per block) ----
    for (int i = tid; i < DD * DD; i += TPB) {
        int k = i / DD, j = i % DD;
        float m1 = 0.0f, g = 0.0f;
        #pragma unroll
        for (int m = 0; m < DD; m++) {
            m1 = fmaf(sWf[m * DD + k], sRf[m * DD + j], m1);
            g  = fmaf(sWf[m * DD + k], sWf[m * DD + j], g);
        }
        sM1f[i] = m1;
        sTf[i]  = (j > k) ? (2.0f * g) : ((j == k) ? g : 0.0f);
    }
    if (tid < DD) {
        float c = 1.0f, wcs = 0.0f, u = 0.0f;
        #pragma unroll
        for (int m = 0; m < DD; m++) {
            c   = fmaf(sbf[m], sRf[m * DD + tid], c);
            wcs += sWf[m * DD + tid];
            u   = fmaf(sWf[m * DD + tid], sbf[m], u);
        }
        sc1f[tid]  = c;
        swcsf[tid] = wcs;
        su2f[tid]  = 2.0f * u;
    }
    __syncthreads();

    const ulonglong2* sM1v = (const ulonglong2*)sM1f;   // [k*5 + jp2], 2 j-pairs each
    const u64*        sc1v = (const u64*)sc1f;          // 10 j-pairs
    const ulonglong2* wcsv = (const ulonglong2*)swcsf;  // 5
    const ulonglong2* u2v  = (const ulonglong2*)su2f;   // 5

    float sl = 0.0f, ql = 0.0f;
    const long long rowsTotal = (long long)B;

    #pragma unroll 1
    for (long long tile = blockIdx.x; tile * ROWS_PER_TILE < rowsTotal; tile += GRID) {
        long long row0 = tile * ROWS_PER_TILE + (long long)tid * 4;
        if (row0 + 4 <= rowsTotal) {
            const float4* xp = (const float4*)(x + row0 * DD);

            // accumulators: j-pairs per row
            u64 a0[DD/2], a1[DD/2], a2[DD/2], a3[DD/2];
            #pragma unroll
            for (int jp = 0; jp < DD/2; jp++) {
                u64 c = sc1v[jp];
                a0[jp] = c; a1[jp] = c; a2[jp] = c; a3[jp] = c;
            }

            // stream x (one float4 per row per i-step, prefetch next)
            float4 A0 = xp[0], B0 = xp[5], C0 = xp[10], D0 = xp[15];
            #pragma unroll
            for (int i = 0; i < 5; i++) {
                float4 A1, B1, C1, D1;
                if (i < 4) { A1 = xp[i+1]; B1 = xp[6+i]; C1 = xp[11+i]; D1 = xp[16+i]; }
                #pragma unroll
                for (int c = 0; c < 4; c++) {
                    const int k = 4 * i + c;
                    float x0 = comp(A0,c), x1 = comp(B0,c), x2 = comp(C0,c), x3 = comp(D0,c);
                    u64 xv0 = pk(x0, x0), xv1 = pk(x1, x1), xv2 = pk(x2, x2), xv3 = pk(x3, x3);
                    #pragma unroll
                    for (int jp2 = 0; jp2 < 5; jp2++) {
                        ulonglong2 w = sM1v[k * 5 + jp2];   // 4 distinct weights
                        a0[2*jp2+0] = fma2(xv0, w.x, a0[2*jp2+0]);
                        a1[2*jp2+0] = fma2(xv1, w.x, a1[2*jp2+0]);
                        a2[2*jp2+0] = fma2(xv2, w.x, a2[2*jp2+0]);
                        a3[2*jp2+0] = fma2(xv3, w.x, a3[2*jp2+0]);
                        a0[2*jp2+1] = fma2(xv0, w.y, a0[2*jp2+1]);
                        a1[2*jp2+1] = fma2(xv1, w.y, a1[2*jp2+1]);
                        a2[2*jp2+1] = fma2(xv2, w.y, a2[2*jp2+1]);
                        a3[2*jp2+1] = fma2(xv3, w.y, a3[2*jp2+1]);
                    }
                }
                A0 = A1; B0 = B1; C0 = C1; D0 = D1;
            }
            #pragma unroll
            for (int jp = 0; jp < DD/2; jp++) {
                a0[jp] = relu2(a0[jp]); a1[jp] = relu2(a1[jp]);
                a2[jp] = relu2(a2[jp]); a3[jp] = relu2(a3[jp]);
            }

            // linear terms: S += wcs.h ; Q += (2 W^T b).h  (j-pair dot)
            u64 s0 = 0ULL, s1 = 0ULL, s2v = 0ULL, s3 = 0ULL;
            u64 q0 = 0ULL, q1 = 0ULL, q2v = 0ULL, q3 = 0ULL;
            #pragma unroll
            for (int jp2 = 0; jp2 < 5; jp2++) {
                ulonglong2 wc = wcsv[jp2];
                ulonglong2 uu = u2v[jp2];
                s0 = fma2(a0[2*jp2+0], wc.x, s0);  s0 = fma2(a0[2*jp2+1], wc.y, s0);
                s1 = fma2(a1[2*jp2+0], wc.x, s1);  s1 = fma2(a1[2*jp2+1], wc.y, s1);
                s2v= fma2(a2[2*jp2+0], wc.x, s2v); s2v= fma2(a2[2*jp2+1], wc.y, s2v);
                s3 = fma2(a3[2*jp2+0], wc.x, s3);  s3 = fma2(a3[2*jp2+1], wc.y, s3);
                q0 = fma2(a0[2*jp2+0], uu.x, q0);  q0 = fma2(a0[2*jp2+1], uu.y, q0);
                q1 = fma2(a1[2*jp2+0], uu.x, q1);  q1 = fma2(a1[2*jp2+1], uu.y, q1);
                q2v= fma2(a2[2*jp2+0], uu.x, q2v); q2v= fma2(a2[2*jp2+1], uu.y, q2v);
                q3 = fma2(a3[2*jp2+0], uu.x, q3);  q3 = fma2(a3[2*jp2+1], uu.y, q3);
            }

            // quadratic: Q += sum_i h_i * (T h)_i, T upper-tri, k-pair dot per row i
            float qs0 = 0.0f, qs1 = 0.0f, qs2 = 0.0f, qs3 = 0.0f;
            #pragma unroll
            for (int i = 0; i < DD; i++) {
                const int kp0 = i >> 1;        // T[i][k]=0 below diag; pair (i-1,i) safe for odd i
                const u64* Trow = (const u64*)(sTf + i * DD);
                u64 y0 = 0ULL, y1 = 0ULL, y2 = 0ULL, y3 = 0ULL;
                #pragma unroll
                for (int kp = kp0; kp < DD/2; kp++) {
                    u64 w = Trow[kp];
                    y0 = fma2(a0[kp], w, y0);
                    y1 = fma2(a1[kp], w, y1);
                    y2 = fma2(a2[kp], w, y2);
                    y3 = fma2(a3[kp], w, y3);
                }
                float lo, hi, h;
                upk(y0, lo, hi); upk(a0[i >> 1], h, h); { float hl, hh; upk(a0[i>>1], hl, hh); h = (i & 1) ? hh : hl; }
                qs0 = fmaf(h, lo + hi, qs0);
                upk(y1, lo, hi); { float hl, hh; upk(a1[i>>1], hl, hh); h = (i & 1) ? hh : hl; }
                qs1 = fmaf(h, lo + hi, qs1);
                upk(y2, lo, hi); { float hl, hh; upk(a2[i>>1], hl, hh); h = (i & 1) ? hh : hl; }
                qs2 = fmaf(h, lo + hi, qs2);
                upk(y3, lo, hi); { float hl, hh; upk(a3[i>>1], hl, hh); h = (i & 1) ? hh : hl; }
                qs3 = fmaf(h, lo + hi, qs3);
            }

            float lo, hi;
            upk(s0, lo, hi); sl += lo + hi;
            upk(s1, lo, hi); sl += lo + hi;
            upk(s2v, lo, hi); sl += lo + hi;
            upk(s3, lo, hi); sl += lo + hi;
            upk(q0, lo, hi); ql += lo + hi + qs0;
            upk(q1, lo, hi); ql += lo + hi + qs1;
            upk(q2v, lo, hi); ql += lo + hi + qs2;
            upk(q3, lo, hi); ql += lo + hi + qs3;
        } else if (row0 < rowsTotal) {
            // scalar tail
            for (long long r = row0; r < rowsTotal && r < row0 + 4; r++) {
                const float* xr = x + r * DD;
                float h[DD];
                #pragma unroll
                for (int j = 0; j < DD; j++) h[j] = sc1f[j];
                for (int k = 0; k < DD; k++) {
                    float xv = xr[k];
                    #pragma unroll
                    for (int j = 0; j < DD; j++) h[j] = fmaf(xv, sM1f[k * DD + j], h[j]);
                }
                #pragma unroll
                for (int j = 0; j < DD; j++) h[j] = fmaxf(h[j], 0.0f);
                #pragma unroll
                for (int k = 0; k < DD; k++) {
                    sl = fmaf(h[k], swcsf[k], sl);
                    ql = fmaf(h[k], su2f[k], ql);
                }
                for (int i = 0; i < DD; i++) {
                    float y = 0.0f;
                    for (int k = i; k < DD; k++) y = fmaf(h[k], sTf[i * DD + k], y);
                    ql = fmaf(h[i], y, ql);
                }
            }
        }
    }

    // ---- deterministic block reduction ----
    redS[tid] = (double)sl;
    redQ[tid] = (double)ql;
    __syncthreads();
    for (int s = TPB / 2; s > 0; s >>= 1) {
        if (tid < s) { redS[tid] += redS[tid + s]; redQ[tid] += redQ[tid + s]; }
        __syncthreads();
    }
    if (tid == 0) {
        g_pS[blockIdx.x] = redS[0];
        g_pQ[blockIdx.x] = redQ[0];
        __threadfence();
        unsigned int t = atomicAdd(&g_ticket, 1u);
        sIsLast = (t == (unsigned int)(GRID - 1)) ? 1 : 0;
    }
    __syncthreads();

    // ---- last block: global reduce + scalar postlude ----
    if (sIsLast) {
        __threadfence();
        double s = 0.0, q = 0.0;
        for (int i = tid; i < GRID; i += TPB) { s += g_pS[i]; q += g_pQ[i]; }
        redS[tid] = s; redQ[tid] = q;
        __syncthreads();
        for (int st = TPB / 2; st > 0; st >>= 1) {
            if (tid < st) { redS[tid] += redS[tid + st]; redQ[tid] += redQ[tid + st]; }
            __syncthreads();
        }
        if (tid == 0) {
            double sb = 0.0, bb = 0.0;
            #pragma unroll
            for (int m = 0; m < DD; m++) { sb += (double)sbf[m]; bb += (double)sbf[m] * (double)sbf[m]; }
            double S = redS[0] + (double)B * sb;
            double Q = redQ[0] + (double)B * bb;
            float n = (float)sqrt(Q);
            int k = 0;
            while (n > 1.0f && k < 300) { n *= 0.5f; k++; }   // exact halvings in fp32
            float mult = (n < 0.8f) ? 10.0f : 1.0f;
            double scale = ldexp(1.0, -k);
            out[0] = (float)(S * scale * (double)mult);
            g_ticket = 0;
        }
    }
}

// ---------------- entry point ----------------
extern "C" void kernel_launch(void* const* d_in, const int* in_sizes, int n_in,
                              void* d_out, int out_size) {
    const float* x = (const float*)d_in[0];
    const float* W = (const float*)d_in[1];
    const float* b = (const float*)d_in[2];
    const float* R = (const float*)d_in[3];
    int B = in_sizes[0] / DD;

    main_kernel<<<GRID, TPB>>>(x, W, b, R, (float*)d_out, B);
}